// round 13
// baseline (speedup 1.0000x reference)
#include <cuda_runtime.h>
#include <cuda_bf16.h>
#include <cstdint>
#include <stdint.h>
#include <math.h>

// Problem constants
#define B_  4
#define T_  4096
#define C_  1024
#define H_  16
#define D_  64
#define CS_ 64
#define NC_ 64
#define M_  (B_ * T_)      // 16384
#define F_  (3 * C_)       // 3072

// Scratch (device globals — no allocs)
__device__ float         g_qkv[50331648];   // [B,T,3C] f32, 192MB
__device__ __nv_bfloat16 g_xh[16777216], g_xl[16777216];     // x split
__device__ __nv_bfloat16 g_wah[3145728], g_wal[3145728];     // w_attn split
__device__ __nv_bfloat16 g_wph[1048576], g_wpl[1048576];     // w_proj split
__device__ __nv_bfloat16 g_yh[16777216], g_yl[16777216];     // y split

// Split a float pair into bf16x2 hi and bf16x2 lo (lo = round(x - hi)).
__device__ __forceinline__ void split2(float x0, float x1,
                                       uint32_t& hi, uint32_t& lo) {
    __nv_bfloat162 h = __floats2bfloat162_rn(x0, x1);
    float r0 = x0 - __bfloat162float(h.x);
    float r1 = x1 - __bfloat162float(h.y);
    __nv_bfloat162 l = __floats2bfloat162_rn(r0, r1);
    hi = *(uint32_t*)&h;
    lo = *(uint32_t*)&l;
}

#define MMA_BF16(d, a, b)                                                     \
    asm volatile(                                                             \
        "mma.sync.aligned.m16n8k16.row.col.f32.bf16.bf16.f32 "                \
        "{%0,%1,%2,%3}, {%4,%5,%6,%7}, {%8,%9}, {%0,%1,%2,%3};"               \
        : "+f"(d[0]), "+f"(d[1]), "+f"(d[2]), "+f"(d[3])                      \
        : "r"(a[0]), "r"(a[1]), "r"(a[2]), "r"(a[3]), "r"(b[0]), "r"(b[1]))

// ---------------------------------------------------------------------------
// Elementwise split: f32 -> bf16 hi + bf16 lo. 4 elems per thread.
// ---------------------------------------------------------------------------
__global__ void __launch_bounds__(256) split_kernel(const float* __restrict__ in,
                                                    __nv_bfloat16* __restrict__ hi,
                                                    __nv_bfloat16* __restrict__ lo,
                                                    int n4)
{
    int i = blockIdx.x * blockDim.x + threadIdx.x;
    if (i < n4) {
        float4 v = ((const float4*)in)[i];
        uint32_t h0, l0, h1, l1;
        split2(v.x, v.y, h0, l0);
        split2(v.z, v.w, h1, l1);
        ((uint2*)hi)[i] = make_uint2(h0, h1);
        ((uint2*)lo)[i] = make_uint2(l0, l1);
    }
}

// ---------------------------------------------------------------------------
// TN GEMM, 3xBF16 split inputs PRE-CONVERTED: Ah/Al [M,K] bf16 rm,
// Bh/Bl [N,K] bf16 rm, C = A @ B^T f32. 128x128 tile, BK=16, 256 thr
// (8 warps = 4m x 2n), double-buffered, hi/lo interleaved for v2 LDS.
// ---------------------------------------------------------------------------
__global__ void __launch_bounds__(256, 2) gemm_tn_bf16(
    const __nv_bfloat16* __restrict__ Ah, const __nv_bfloat16* __restrict__ Al,
    const __nv_bfloat16* __restrict__ Bh, const __nv_bfloat16* __restrict__ Bl,
    float* __restrict__ C, int M, int N, int K)
{
    // words: [buf][side A/B][kpair 0..7][row 0..135][hi/lo]
    __shared__ uint32_t sm[2][2][8][136][2];   // 34,816 B

    const int tid  = threadIdx.x;
    const int row0 = blockIdx.y * 128;
    const int col0 = blockIdx.x * 128;

    const int lane = tid & 31;
    const int warp = tid >> 5;
    const int gid  = lane >> 2;         // 0..7
    const int tig  = lane & 3;          // 0..3
    const int mb   = (warp & 3) * 32;   // warp m offset
    const int nb   = (warp >> 2) * 64;  // warp n offset

    // staging map: side = tid>>7 (0=A,1=B), row = tid&127; 16 k per step
    const int side = tid >> 7;
    const int srow = tid & 127;
    const __nv_bfloat16* pH = side ? Bh + (size_t)(col0 + srow) * K
                                   : Ah + (size_t)(row0 + srow) * K;
    const __nv_bfloat16* pL = side ? Bl + (size_t)(col0 + srow) * K
                                   : Al + (size_t)(row0 + srow) * K;

    float acc[2][8][4];
#pragma unroll
    for (int i = 0; i < 2; i++)
#pragma unroll
        for (int j = 0; j < 8; j++)
#pragma unroll
            for (int r = 0; r < 4; r++) acc[i][j][r] = 0.0f;

    const int nK = K >> 4;
    uint4 ph0, ph1, pl0, pl1;

    // prologue: stage k-step 0 into buffer 0
    ph0 = *(const uint4*)(pH);      ph1 = *(const uint4*)(pH + 8);
    pl0 = *(const uint4*)(pL);      pl1 = *(const uint4*)(pL + 8);
    {
        uint32_t hw[8] = {ph0.x, ph0.y, ph0.z, ph0.w, ph1.x, ph1.y, ph1.z, ph1.w};
        uint32_t lw[8] = {pl0.x, pl0.y, pl0.z, pl0.w, pl1.x, pl1.y, pl1.z, pl1.w};
#pragma unroll
        for (int q = 0; q < 8; q++)
            *(uint2*)&sm[0][side][q][srow][0] = make_uint2(hw[q], lw[q]);
    }
    __syncthreads();

    int buf = 0;
    for (int ks = 0; ks < nK; ks++) {
        const bool has_next = (ks + 1 < nK);
        if (has_next) {
            int kg = (ks + 1) << 4;
            ph0 = *(const uint4*)(pH + kg);  ph1 = *(const uint4*)(pH + kg + 8);
            pl0 = *(const uint4*)(pL + kg);  pl1 = *(const uint4*)(pL + kg + 8);
        }

        // ---- consume current buffer ----
        {
            uint32_t Af[2][2][4];   // [i][hi/lo][frag]
#pragma unroll
            for (int i = 0; i < 2; i++) {
                int m0 = mb + i * 16 + gid;
                uint2 t0 = *(uint2*)&sm[buf][0][tig][m0][0];
                uint2 t1 = *(uint2*)&sm[buf][0][tig][m0 + 8][0];
                uint2 t2 = *(uint2*)&sm[buf][0][tig + 4][m0][0];
                uint2 t3 = *(uint2*)&sm[buf][0][tig + 4][m0 + 8][0];
                Af[i][0][0] = t0.x; Af[i][1][0] = t0.y;
                Af[i][0][1] = t1.x; Af[i][1][1] = t1.y;
                Af[i][0][2] = t2.x; Af[i][1][2] = t2.y;
                Af[i][0][3] = t3.x; Af[i][1][3] = t3.y;
            }
#pragma unroll
            for (int j = 0; j < 8; j++) {
                int n0 = nb + j * 8 + gid;
                uint2 u0 = *(uint2*)&sm[buf][1][tig][n0][0];
                uint2 u1 = *(uint2*)&sm[buf][1][tig + 4][n0][0];
                uint32_t Bh_[2] = {u0.x, u1.x};
                uint32_t Bl_[2] = {u0.y, u1.y};
#pragma unroll
                for (int i = 0; i < 2; i++) {
                    MMA_BF16(acc[i][j], Af[i][0], Bh_);   // hi*hi
                    MMA_BF16(acc[i][j], Af[i][0], Bl_);   // hi*lo
                    MMA_BF16(acc[i][j], Af[i][1], Bh_);   // lo*hi
                }
            }
        }

        // ---- stage next into other buffer ----
        if (has_next) {
            int nb2 = buf ^ 1;
            uint32_t hw[8] = {ph0.x, ph0.y, ph0.z, ph0.w, ph1.x, ph1.y, ph1.z, ph1.w};
            uint32_t lw[8] = {pl0.x, pl0.y, pl0.z, pl0.w, pl1.x, pl1.y, pl1.z, pl1.w};
#pragma unroll
            for (int q = 0; q < 8; q++)
                *(uint2*)&sm[nb2][side][q][srow][0] = make_uint2(hw[q], lw[q]);
        }
        __syncthreads();
        buf ^= 1;
    }

    // epilogue
#pragma unroll
    for (int i = 0; i < 2; i++) {
        int row = row0 + mb + i * 16 + gid;
#pragma unroll
        for (int j = 0; j < 8; j++) {
            int col = col0 + nb + j * 8 + tig * 2;
            *(float2*)(C + (size_t)row * N + col) =
                make_float2(acc[i][j][0], acc[i][j][1]);
            *(float2*)(C + (size_t)(row + 8) * N + col) =
                make_float2(acc[i][j][2], acc[i][j][3]);
        }
    }
}

// ---------------------------------------------------------------------------
// Fused chunked attention: one block per (b, chunk, head).
// Writes y pre-split as bf16 hi/lo (feeds the proj GEMM directly).
// ---------------------------------------------------------------------------
__global__ void __launch_bounds__(256) attn_kernel(const float* __restrict__ qkv,
                                                   __nv_bfloat16* __restrict__ yh,
                                                   __nv_bfloat16* __restrict__ yl)
{
    extern __shared__ float smf[];
    float* qs = smf;                 // [64][65]
    float* ks = smf + 64 * 65;
    float* vs = smf + 2 * 64 * 65;
    float* ps = smf + 3 * 64 * 65;

    const int tid = threadIdx.x;
    const int blk = blockIdx.x;
    const int b = blk >> 10;          // NC_*H_ = 1024
    const int n = (blk >> 4) & 63;
    const int h = blk & 15;

    const float neg_ln_base_over_half = -9.210340371976184f / 32.0f; // -ln(10000)/32
    for (int idx = tid; idx < 64 * 32; idx += 256) {
        int r = idx >> 5;       // 0..63
        int j = idx & 31;       // 0..31
        const float* rowp = qkv + ((size_t)(b * T_ + n * 64 + r)) * 3072 + h * 64;
        float q1 = rowp[j],        q2 = rowp[j + 32];
        float k1 = rowp[1024 + j], k2 = rowp[1024 + j + 32];
        float invf = expf((float)j * neg_ln_base_over_half);   // 10000^(-j/32)
        float ang  = (float)r * invf;
        float cv, sv;
        sincosf(ang, &sv, &cv);   // sv = sin, cv = cos
        qs[r * 65 + j]      =  q1 * cv + q2 * sv;
        qs[r * 65 + j + 32] = -q1 * sv + q2 * cv;
        ks[r * 65 + j]      =  k1 * cv + k2 * sv;
        ks[r * 65 + j + 32] = -k1 * sv + k2 * cv;
    }
    for (int idx = tid; idx < 64 * 64; idx += 256) {
        int r  = idx >> 6;
        int dd = idx & 63;
        vs[r * 65 + dd] =
            qkv[((size_t)(b * T_ + n * 64 + r)) * 3072 + 2048 + h * 64 + dd];
    }
    __syncthreads();

    const int r0 = (tid >> 4) << 2;   // row block
    const int c0 = (tid & 15) << 2;   // col block (also d0 for y)

    {
        float sc[4][4];
#pragma unroll
        for (int i = 0; i < 4; i++)
#pragma unroll
            for (int j = 0; j < 4; j++) sc[i][j] = 0.0f;
#pragma unroll 8
        for (int dd = 0; dd < 64; dd++) {
            float aq[4], bk[4];
#pragma unroll
            for (int i = 0; i < 4; i++) aq[i] = qs[(r0 + i) * 65 + dd];
#pragma unroll
            for (int j = 0; j < 4; j++) bk[j] = ks[(c0 + j) * 65 + dd];
#pragma unroll
            for (int i = 0; i < 4; i++)
#pragma unroll
                for (int j = 0; j < 4; j++)
                    sc[i][j] += aq[i] * bk[j];
        }
#pragma unroll
        for (int i = 0; i < 4; i++)
#pragma unroll
            for (int j = 0; j < 4; j++)
                ps[(r0 + i) * 65 + c0 + j] = sc[i][j] * 0.125f;
    }
    __syncthreads();

    if (tid < 64) {
        float* row = ps + tid * 65;
        float mx = -1e30f;
#pragma unroll 8
        for (int c = 0; c < 64; c++) mx = fmaxf(mx, row[c]);
        float sum = 0.0f;
#pragma unroll 8
        for (int c = 0; c < 64; c++) {
            float e = expf(row[c] - mx);
            row[c] = e;
            sum += e;
        }
        float inv = 1.0f / sum;
#pragma unroll 8
        for (int c = 0; c < 64; c++) row[c] *= inv;
    }
    __syncthreads();

    {
        float acc[4][4];
#pragma unroll
        for (int i = 0; i < 4; i++)
#pragma unroll
            for (int j = 0; j < 4; j++) acc[i][j] = 0.0f;
#pragma unroll 8
        for (int c = 0; c < 64; c++) {
            float pv[4], vv[4];
#pragma unroll
            for (int i = 0; i < 4; i++) pv[i] = ps[(r0 + i) * 65 + c];
#pragma unroll
            for (int j = 0; j < 4; j++) vv[j] = vs[c * 65 + c0 + j];
#pragma unroll
            for (int i = 0; i < 4; i++)
#pragma unroll
                for (int j = 0; j < 4; j++)
                    acc[i][j] += pv[i] * vv[j];
        }
#pragma unroll
        for (int i = 0; i < 4; i++) {
            size_t e = ((size_t)(b * T_ + n * 64 + r0 + i)) * 1024 + h * 64 + c0;
            uint32_t h0, l0, h1, l1;
            split2(acc[i][0], acc[i][1], h0, l0);
            split2(acc[i][2], acc[i][3], h1, l1);
            *(uint2*)(yh + e) = make_uint2(h0, h1);
            *(uint2*)(yl + e) = make_uint2(l0, l1);
        }
    }
}

// ---------------------------------------------------------------------------
extern "C" void kernel_launch(void* const* d_in, const int* in_sizes, int n_in,
                              void* d_out, int out_size)
{
    // Bind inputs BY ELEMENT COUNT (pairwise-distinct sizes):
    //   x : 16,777,216   w_attn : 3,145,728   w_proj : 1,048,576
    const float* x      = nullptr;
    const float* w_attn = nullptr;
    const float* w_proj = nullptr;
    for (int i = 0; i < n_in; i++) {
        int sz = in_sizes[i];
        if      (sz == M_ * C_) x      = (const float*)d_in[i];
        else if (sz == F_ * C_) w_attn = (const float*)d_in[i];
        else if (sz == C_ * C_) w_proj = (const float*)d_in[i];
    }
    if (!x)      x      = (const float*)d_in[0];
    if (!w_attn) w_attn = (const float*)d_in[1];
    if (!w_proj) w_proj = (const float*)d_in[2];

    float* out = (float*)d_out;

    float *qkv_ptr;
    __nv_bfloat16 *xh, *xl, *wah, *wal, *wph, *wpl, *yh, *yl;
    cudaGetSymbolAddress((void**)&qkv_ptr, g_qkv);
    cudaGetSymbolAddress((void**)&xh,  g_xh);  cudaGetSymbolAddress((void**)&xl,  g_xl);
    cudaGetSymbolAddress((void**)&wah, g_wah); cudaGetSymbolAddress((void**)&wal, g_wal);
    cudaGetSymbolAddress((void**)&wph, g_wph); cudaGetSymbolAddress((void**)&wpl, g_wpl);
    cudaGetSymbolAddress((void**)&yh,  g_yh);  cudaGetSymbolAddress((void**)&yl,  g_yl);

    const int attn_smem = 4 * 64 * 65 * sizeof(float); // 66560 bytes
    cudaFuncSetAttribute(attn_kernel, cudaFuncAttributeMaxDynamicSharedMemorySize,
                         attn_smem);

    // pre-split inputs into bf16 hi/lo
    split_kernel<<<(M_ * C_ / 4 + 255) / 256, 256>>>(x, xh, xl, M_ * C_ / 4);
    split_kernel<<<(F_ * C_ / 4 + 255) / 256, 256>>>(w_attn, wah, wal, F_ * C_ / 4);
    split_kernel<<<(C_ * C_ / 4 + 255) / 256, 256>>>(w_proj, wph, wpl, C_ * C_ / 4);

    // qkv = x @ w_attn^T   (M=16384, N=3072, K=1024)
    gemm_tn_bf16<<<dim3(F_ / 128, M_ / 128), 256>>>(xh, xl, wah, wal, qkv_ptr,
                                                    M_, F_, C_);
    // chunked attention with RoPE; emits y pre-split
    attn_kernel<<<B_ * NC_ * H_, 256, attn_smem>>>(qkv_ptr, yh, yl);
    // out = y @ w_proj^T   (M=16384, N=1024, K=1024)
    gemm_tn_bf16<<<dim3(C_ / 128, M_ / 128), 256>>>(yh, yl, wph, wpl, out,
                                                    M_, C_, C_);
}